// round 7
// baseline (speedup 1.0000x reference)
#include <cuda_runtime.h>
#include <cstdint>

#define LN_EPS 1e-5f
#define EPS_ATTN 1e-8f
#define SCALE 0.08838834764831845f
typedef unsigned long long ull;

__device__ __forceinline__ ull fma2(ull a, ull b, ull c){ ull d; asm("fma.rn.f32x2 %0,%1,%2,%3;":"=l"(d):"l"(a),"l"(b),"l"(c)); return d; }
__device__ __forceinline__ ull add2(ull a, ull b){ ull d; asm("add.rn.f32x2 %0,%1,%2;":"=l"(d):"l"(a),"l"(b)); return d; }
__device__ __forceinline__ ull pk2(float lo, float hi){ ull d; asm("mov.b64 %0,{%1,%2};":"=l"(d):"f"(lo),"f"(hi)); return d; }
__device__ __forceinline__ void unpk(ull v, float&lo, float&hi){ asm("mov.b64 {%0,%1},%2;":"=f"(lo),"=f"(hi):"l"(v)); }
__device__ __forceinline__ float up2(ull v){ float a,b; unpk(v,a,b); return a+b; }

__device__ float g_slots_n[131072];
__device__ float g_qk[131072];
__device__ float g_qksum[1024];
__device__ float g_part[4194304];   // [b][tile][s][128]
__device__ float g_cs[32768];
__device__ float g_cb[32768];

// ---- 512-thread kernels: group g = t>>7 owns slots {g, g+4} ----
__device__ __forceinline__ float gsum512(float v, int t, volatile float* red){
    #pragma unroll
    for(int o=16;o>0;o>>=1) v += __shfl_xor_sync(0xffffffffu,v,o);
    if((t&31)==0) red[t>>5]=v;
    __syncthreads();
    int g4=(t>>7)<<2;
    v = red[g4]+red[g4+1]+red[g4+2]+red[g4+3];
    __syncthreads();
    return v;
}

// LN(o) -> SN, q = SN@Wq.T, qk = q@Wk, qksum. All 512 threads participate.
__device__ __forceinline__ void project512(int b, int t, float o0, float o1,
    float (*SN)[128], float (*Qs)[128], volatile float* red,
    const float* __restrict__ Wq, const float* __restrict__ Wk)
{
    int t1=t&127, g=t>>7, s0=g, s1=g+4;
    float m0=gsum512(o0,t,red)*(1.f/128.f);
    float d0=o0-m0;
    float v0=gsum512(d0*d0,t,red)*(1.f/128.f);
    float sn0=d0*rsqrtf(v0+LN_EPS);
    float m1=gsum512(o1,t,red)*(1.f/128.f);
    float d1=o1-m1;
    float v1=gsum512(d1*d1,t,red)*(1.f/128.f);
    float sn1=d1*rsqrtf(v1+LN_EPS);
    SN[s0][t1]=sn0; SN[s1][t1]=sn1;
    g_slots_n[(b*8+s0)*128+t1]=sn0;
    g_slots_n[(b*8+s1)*128+t1]=sn1;
    __syncthreads();
    ull q0=0ull,q1=0ull;
    const ulonglong2* wq=(const ulonglong2*)(Wq+(size_t)t1*128);
    const ulonglong2* x0=(const ulonglong2*)SN[s0];
    const ulonglong2* x1=(const ulonglong2*)SN[s1];
    #pragma unroll 8
    for(int c=0;c<32;c++){ ulonglong2 w=wq[c], a=x0[c], bb=x1[c];
        q0=fma2(w.x,a.x,q0); q0=fma2(w.y,a.y,q0);
        q1=fma2(w.x,bb.x,q1); q1=fma2(w.y,bb.y,q1); }
    Qs[s0][t1]=up2(q0); Qs[s1][t1]=up2(q1);
    __syncthreads();
    float a0=0.f,a1=0.f;
    #pragma unroll 8
    for(int d=0;d<128;d++){ float wk=Wk[d*128+t1];
        a0+=Qs[s0][d]*wk; a1+=Qs[s1][d]*wk; }
    g_qk[(b*8+s0)*128+t1]=a0;
    g_qk[(b*8+s1)*128+t1]=a1;
    float qs0=gsum512(a0,t,red);
    float qs1=gsum512(a1,t,red);
    if(t1==0){ g_qksum[b*8+s0]=qs0; g_qksum[b*8+s1]=qs1; }
}

__global__ void __launch_bounds__(512) k_init_proj(
    const float* __restrict__ noise, const float* __restrict__ mu, const float* __restrict__ ls,
    const float* __restrict__ Wq, const float* __restrict__ Wk)
{
    __shared__ __align__(16) float SN[8][128];
    __shared__ __align__(16) float Qs[8][128];
    __shared__ volatile float red[16];
    int b=blockIdx.x, t=threadIdx.x, t1=t&127, g=t>>7;
    float e=expf(ls[t1]); float m=mu[t1];
    float o0=m+e*noise[(b*8+g  )*128+t1];
    float o1=m+e*noise[(b*8+g+4)*128+t1];
    project512(b,t,o0,o1,SN,Qs,red,Wq,Wk);
}

// ---- attention: grid(32,128), 256 threads, dyn smem ----
__global__ void __launch_bounds__(256,2) k_attn(const float* __restrict__ inputs){
    extern __shared__ float sm[];
    float* XS  = sm;               // 128*132
    float* QK  = XS + 16896;       // 1024
    float* LG  = QK + 1024;        // 1024 raw dots
    float* AA  = LG + 1024;        // 1024
    float* QS  = AA + 1024;        // 8
    float* CW  = QS + 8;           // 32
    float* CBv = CW + 32;          // 32
    float* MUb = CBv + 32;         // 128
    float* RSb = MUb + 128;        // 128
    float* PART= RSb + 128;        // 8*8*128
    const int t=threadIdx.x, lane=t&31, w=t>>5;
    const int tile=blockIdx.x, b=blockIdx.y;
    const int row=t&127, h=t>>7, sb=h<<2, ob=4-sb;

    { const float4* gsrc=(const float4*)(inputs + ((size_t)b*4096 + tile*128)*128);
      #pragma unroll 16
      for(int j=t;j<4096;j+=256){ int r=j>>5,c=j&31; *(float4*)(XS+r*132+c*4)=gsrc[j]; } }
    { int s=t>>5, i=lane*4;
      *(float4*)(QK+s*128+i)=*(const float4*)(g_qk+(b*8+s)*128+i);
      if(t<8) QS[t]=g_qksum[b*8+t]; }
    __syncthreads();

    // phase 2: thread (h,row) computes dots for slots sb..sb+3 of its row
    float dd[4], mu=0.f, rstd=0.f, at[4];
    {
        ull pd[4]={0ull,0ull,0ull,0ull}, s1=0ull, s2=0ull;
        const ulonglong2* xp=(const ulonglong2*)(XS+row*132);
        const ulonglong2* q0=(const ulonglong2*)(QK+(sb+0)*128);
        const ulonglong2* q1=(const ulonglong2*)(QK+(sb+1)*128);
        const ulonglong2* q2=(const ulonglong2*)(QK+(sb+2)*128);
        const ulonglong2* q3=(const ulonglong2*)(QK+(sb+3)*128);
        #pragma unroll 4
        for(int c=0;c<32;c++){
            ulonglong2 xv=xp[c];
            if(h==0){
                s1=add2(s1,xv.x); s1=add2(s1,xv.y);
                s2=fma2(xv.x,xv.x,s2); s2=fma2(xv.y,xv.y,s2);
            }
            ulonglong2 qv;
            qv=q0[c]; pd[0]=fma2(xv.x,qv.x,pd[0]); pd[0]=fma2(xv.y,qv.y,pd[0]);
            qv=q1[c]; pd[1]=fma2(xv.x,qv.x,pd[1]); pd[1]=fma2(xv.y,qv.y,pd[1]);
            qv=q2[c]; pd[2]=fma2(xv.x,qv.x,pd[2]); pd[2]=fma2(xv.y,qv.y,pd[2]);
            qv=q3[c]; pd[3]=fma2(xv.x,qv.x,pd[3]); pd[3]=fma2(xv.y,qv.y,pd[3]);
        }
        #pragma unroll
        for(int j=0;j<4;j++){ dd[j]=up2(pd[j]); LG[row*8+sb+j]=dd[j]; }
        if(h==0){
            float sum=up2(s1), sumsq=up2(s2);
            mu=sum*(1.f/128.f);
            float var=sumsq*(1.f/128.f)-mu*mu;
            rstd=rsqrtf(var+LN_EPS);
            MUb[row]=mu; RSb[row]=rstd;
        }
    }
    __syncthreads();
    {
        if(h==1){ mu=MUb[row]; rstd=RSb[row]; }
        float lg8[8];
        #pragma unroll
        for(int j=0;j<4;j++) lg8[sb+j]=SCALE*rstd*(dd[j]-mu*QS[sb+j]);
        #pragma unroll
        for(int j=0;j<4;j++) lg8[ob+j]=SCALE*rstd*(LG[row*8+ob+j]-mu*QS[ob+j]);
        float m=lg8[0];
        #pragma unroll
        for(int k=1;k<8;k++) m=fmaxf(m,lg8[k]);
        float ee[8], tot=0.f;
        #pragma unroll
        for(int k=0;k<8;k++){ ee[k]=__expf(lg8[k]-m); tot+=ee[k]; }
        float inv=1.f/tot;
        #pragma unroll
        for(int j=0;j<4;j++){
            at[j]=ee[sb+j]*inv+EPS_ATTN;
            AA[row*8+sb+j]=at[j]*rstd;
        }
    }
    // per-warp colsum/csub partials
    #pragma unroll
    for(int j=0;j<4;j++){
        float v=at[j];
        #pragma unroll
        for(int o=16;o>0;o>>=1) v+=__shfl_xor_sync(0xffffffffu,v,o);
        float u=at[j]*rstd*mu;
        #pragma unroll
        for(int o=16;o>0;o>>=1) u+=__shfl_xor_sync(0xffffffffu,u,o);
        if(lane==0){ CW[w*4+j]=v; CBv[w*4+j]=u; }
    }
    __syncthreads();

    // phase 3: warp w -> rows [w*16, w*16+16), lane -> cols lane*4..+3
    ull acc[8][2];
    #pragma unroll
    for(int s=0;s<8;s++){ acc[s][0]=0ull; acc[s][1]=0ull; }
    #pragma unroll 2
    for(int r0=0;r0<16;r0++){
        int r=(w<<4)+r0;
        ulonglong2 xv=*(const ulonglong2*)(XS + r*132 + lane*4);
        const float* a8=AA+r*8;
        float4 alo=*(const float4*)a8, ahi=*(const float4*)(a8+4);
        acc[0][0]=fma2(pk2(alo.x,alo.x),xv.x,acc[0][0]); acc[0][1]=fma2(pk2(alo.x,alo.x),xv.y,acc[0][1]);
        acc[1][0]=fma2(pk2(alo.y,alo.y),xv.x,acc[1][0]); acc[1][1]=fma2(pk2(alo.y,alo.y),xv.y,acc[1][1]);
        acc[2][0]=fma2(pk2(alo.z,alo.z),xv.x,acc[2][0]); acc[2][1]=fma2(pk2(alo.z,alo.z),xv.y,acc[2][1]);
        acc[3][0]=fma2(pk2(alo.w,alo.w),xv.x,acc[3][0]); acc[3][1]=fma2(pk2(alo.w,alo.w),xv.y,acc[3][1]);
        acc[4][0]=fma2(pk2(ahi.x,ahi.x),xv.x,acc[4][0]); acc[4][1]=fma2(pk2(ahi.x,ahi.x),xv.y,acc[4][1]);
        acc[5][0]=fma2(pk2(ahi.y,ahi.y),xv.x,acc[5][0]); acc[5][1]=fma2(pk2(ahi.y,ahi.y),xv.y,acc[5][1]);
        acc[6][0]=fma2(pk2(ahi.z,ahi.z),xv.x,acc[6][0]); acc[6][1]=fma2(pk2(ahi.z,ahi.z),xv.y,acc[6][1]);
        acc[7][0]=fma2(pk2(ahi.w,ahi.w),xv.x,acc[7][0]); acc[7][1]=fma2(pk2(ahi.w,ahi.w),xv.y,acc[7][1]);
    }
    if(t<8){
        int s=t; float cs,cb;
        if(s<4){ cs=CW[s]+CW[4+s]+CW[8+s]+CW[12+s];
                 cb=CBv[s]+CBv[4+s]+CBv[8+s]+CBv[12+s]; }
        else   { int j=s-4;
                 cs=CW[16+j]+CW[20+j]+CW[24+j]+CW[28+j];
                 cb=CBv[16+j]+CBv[20+j]+CBv[24+j]+CBv[28+j]; }
        g_cs[(b*32+tile)*8+s]=cs;
        g_cb[(b*32+tile)*8+s]=cb;
    }
    #pragma unroll
    for(int s=0;s<8;s++)
        *(ulonglong2*)(PART+(w*8+s)*128+lane*4)=make_ulonglong2(acc[s][0],acc[s][1]);
    __syncthreads();
    {
        int s=t>>5, c0=lane*4;
        float o[4];
        #pragma unroll
        for(int j=0;j<4;j++){
            float v=0.f;
            #pragma unroll
            for(int w8=0;w8<8;w8++) v+=PART[(w8*8+s)*128+c0+j];
            o[j]=v;
        }
        *(float4*)(g_part+(((size_t)(b*32+tile)*8+s)*128+c0))=make_float4(o[0],o[1],o[2],o[3]);
    }
}

// ---- fused update + projection: 128 blocks x 512 threads ----
__global__ void __launch_bounds__(512) k_update(
    const float* __restrict__ Wv, const float* __restrict__ W_ih, const float* __restrict__ W_hh,
    const float* __restrict__ b_ih, const float* __restrict__ b_hh,
    const float* __restrict__ W1, const float* __restrict__ b1,
    const float* __restrict__ W2, const float* __restrict__ b2,
    const float* __restrict__ Wq, const float* __restrict__ Wk,
    float* __restrict__ out, int last)
{
    __shared__ __align__(16) float Ts[8][128];
    __shared__ __align__(16) float Us[8][128];
    __shared__ __align__(16) float Hs[8][128];
    __shared__ __align__(16) float H1s[8][256];
    __shared__ __align__(16) float Qs[8][128];
    __shared__ float CSs[8], CBs[8];
    __shared__ volatile float red[16];
    int b=blockIdx.x, t=threadIdx.x, t1=t&127, g=t>>7, s0=g, s1=g+4;

    if(t<8){
        float cs=0.f,cb=0.f;
        #pragma unroll 8
        for(int k=0;k<32;k++){ cs+=g_cs[(b*32+k)*8+t]; cb+=g_cb[(b*32+k)*8+t]; }
        CSs[t]=1.f/cs; CBs[t]=cb;
    }
    __syncthreads();
    {
        float a0=0.f,a1=0.f;
        const float* p0=g_part+(((size_t)b*32*8)+s0)*128+t1;
        const float* p1=g_part+(((size_t)b*32*8)+s1)*128+t1;
        #pragma unroll 8
        for(int k=0;k<32;k++){ a0+=p0[(size_t)k*1024]; a1+=p1[(size_t)k*1024]; }
        Ts[s0][t1]=(a0-CBs[s0])*CSs[s0];
        Ts[s1][t1]=(a1-CBs[s1])*CSs[s1];
        Hs[s0][t1]=g_slots_n[(b*8+s0)*128+t1];
        Hs[s1][t1]=g_slots_n[(b*8+s1)*128+t1];
    }
    __syncthreads();
    {
        ull u0=0ull,u1=0ull;
        const ulonglong2* wv=(const ulonglong2*)(Wv+(size_t)t1*128);
        const ulonglong2* x0=(const ulonglong2*)Ts[s0];
        const ulonglong2* x1=(const ulonglong2*)Ts[s1];
        #pragma unroll 8
        for(int c=0;c<32;c++){ ulonglong2 w=wv[c], a=x0[c], bb=x1[c];
            u0=fma2(w.x,a.x,u0); u0=fma2(w.y,a.y,u0);
            u1=fma2(w.x,bb.x,u1); u1=fma2(w.y,bb.y,u1); }
        Us[s0][t1]=up2(u0); Us[s1][t1]=up2(u1);
    }
    __syncthreads();

    float sd0, sd1, h0r=Hs[s0][t1], h1r=Hs[s1][t1];
    {
        ull Ar0=0,Ar1=0,Az0=0,Az1=0,An0=0,An1=0,Br0=0,Br1=0,Bz0=0,Bz1=0,Bn0=0,Bn1=0;
        const ulonglong2* wi0=(const ulonglong2*)(W_ih+(size_t)t1*128);
        const ulonglong2* wi1=(const ulonglong2*)(W_ih+(size_t)(t1+128)*128);
        const ulonglong2* wi2=(const ulonglong2*)(W_ih+(size_t)(t1+256)*128);
        const ulonglong2* wh0=(const ulonglong2*)(W_hh+(size_t)t1*128);
        const ulonglong2* wh1=(const ulonglong2*)(W_hh+(size_t)(t1+128)*128);
        const ulonglong2* wh2=(const ulonglong2*)(W_hh+(size_t)(t1+256)*128);
        const ulonglong2* pu0=(const ulonglong2*)Us[s0];
        const ulonglong2* pu1=(const ulonglong2*)Us[s1];
        const ulonglong2* ph0=(const ulonglong2*)Hs[s0];
        const ulonglong2* ph1=(const ulonglong2*)Hs[s1];
        #pragma unroll 4
        for(int c=0;c<32;c++){
            ulonglong2 u0v=pu0[c], u1v=pu1[c], h0v=ph0[c], h1v=ph1[c], w;
            w=wi0[c]; Ar0=fma2(w.x,u0v.x,Ar0); Ar0=fma2(w.y,u0v.y,Ar0); Ar1=fma2(w.x,u1v.x,Ar1); Ar1=fma2(w.y,u1v.y,Ar1);
            w=wi1[c]; Az0=fma2(w.x,u0v.x,Az0); Az0=fma2(w.y,u0v.y,Az0); Az1=fma2(w.x,u1v.x,Az1); Az1=fma2(w.y,u1v.y,Az1);
            w=wi2[c]; An0=fma2(w.x,u0v.x,An0); An0=fma2(w.y,u0v.y,An0); An1=fma2(w.x,u1v.x,An1); An1=fma2(w.y,u1v.y,An1);
            w=wh0[c]; Br0=fma2(w.x,h0v.x,Br0); Br0=fma2(w.y,h0v.y,Br0); Br1=fma2(w.x,h1v.x,Br1); Br1=fma2(w.y,h1v.y,Br1);
            w=wh1[c]; Bz0=fma2(w.x,h0v.x,Bz0); Bz0=fma2(w.y,h0v.y,Bz0); Bz1=fma2(w.x,h1v.x,Bz1); Bz1=fma2(w.y,h1v.y,Bz1);
            w=wh2[c]; Bn0=fma2(w.x,h0v.x,Bn0); Bn0=fma2(w.y,h0v.y,Bn0); Bn1=fma2(w.x,h1v.x,Bn1); Bn1=fma2(w.y,h1v.y,Bn1);
        }
        float bi0=b_ih[t1], bi1=b_ih[t1+128], bi2=b_ih[t1+256];
        float bh0=b_hh[t1], bh1=b_hh[t1+128], bh2=b_hh[t1+256];
        float xr0=bi0+up2(Ar0), xz0=bi1+up2(Az0), xn0=bi2+up2(An0);
        float hr0=bh0+up2(Br0), hz0=bh1+up2(Bz0), hn0=bh2+up2(Bn0);
        float xr1=bi0+up2(Ar1), xz1=bi1+up2(Az1), xn1=bi2+up2(An1);
        float hr1=bh0+up2(Br1), hz1=bh1+up2(Bz1), hn1=bh2+up2(Bn1);
        float r0=1.f/(1.f+__expf(-(xr0+hr0)));
        float z0=1.f/(1.f+__expf(-(xz0+hz0)));
        float n0=tanhf(xn0+r0*hn0);
        sd0=(1.f-z0)*n0+z0*h0r;
        float r1=1.f/(1.f+__expf(-(xr1+hr1)));
        float z1=1.f/(1.f+__expf(-(xz1+hz1)));
        float n1=tanhf(xn1+r1*hn1);
        sd1=(1.f-z1)*n1+z1*h1r;
    }
    // MLP: LN(sd) -> Ts (reuse)
    {
        float m0=gsum512(sd0,t,red)*(1.f/128.f);
        float d0=sd0-m0;
        float v0=gsum512(d0*d0,t,red)*(1.f/128.f);
        float m1=gsum512(sd1,t,red)*(1.f/128.f);
        float d1=sd1-m1;
        float v1=gsum512(d1*d1,t,red)*(1.f/128.f);
        Ts[s0][t1]=d0*rsqrtf(v0+LN_EPS);
        Ts[s1][t1]=d1*rsqrtf(v1+LN_EPS);
    }
    __syncthreads();
    {
        ull A00=0,A01=0,A10=0,A11=0;
        const ulonglong2* w1a=(const ulonglong2*)(W1+(size_t)t1*128);
        const ulonglong2* w1b=(const ulonglong2*)(W1+(size_t)(t1+128)*128);
        const ulonglong2* x0=(const ulonglong2*)Ts[s0];
        const ulonglong2* x1=(const ulonglong2*)Ts[s1];
        #pragma unroll 8
        for(int c=0;c<32;c++){
            ulonglong2 a=w1a[c], bb=w1b[c], p=x0[c], q=x1[c];
            A00=fma2(a.x,p.x,A00); A00=fma2(a.y,p.y,A00);
            A01=fma2(bb.x,p.x,A01); A01=fma2(bb.y,p.y,A01);
            A10=fma2(a.x,q.x,A10); A10=fma2(a.y,q.y,A10);
            A11=fma2(bb.x,q.x,A11); A11=fma2(bb.y,q.y,A11);
        }
        float ba=b1[t1], bbv=b1[t1+128];
        H1s[s0][t1]    =fmaxf(ba +up2(A00),0.f);
        H1s[s0][t1+128]=fmaxf(bbv+up2(A01),0.f);
        H1s[s1][t1]    =fmaxf(ba +up2(A10),0.f);
        H1s[s1][t1+128]=fmaxf(bbv+up2(A11),0.f);
    }
    __syncthreads();
    float o0, o1;
    {
        ull O0=0ull,O1=0ull;
        const ulonglong2* w2=(const ulonglong2*)(W2+(size_t)t1*256);
        const ulonglong2* x0=(const ulonglong2*)H1s[s0];
        const ulonglong2* x1=(const ulonglong2*)H1s[s1];
        #pragma unroll 8
        for(int c=0;c<64;c++){
            ulonglong2 w=w2[c], p=x0[c], q=x1[c];
            O0=fma2(w.x,p.x,O0); O0=fma2(w.y,p.y,O0);
            O1=fma2(w.x,q.x,O1); O1=fma2(w.y,q.y,O1);
        }
        float bb=b2[t1];
        o0=sd0+bb+up2(O0);
        o1=sd1+bb+up2(O1);
    }
    out[(b*8+s0)*128+t1]=o0;
    out[(b*8+s1)*128+t1]=o1;
    __syncthreads();
    if(!last) project512(b,t,o0,o1,Hs,Qs,red,Wq,Wk);
}

#define ATTN_SMEM_BYTES 113952

extern "C" void kernel_launch(void* const* d_in, const int* in_sizes, int n_in,
                              void* d_out, int out_size){
    const float* inputs=(const float*)d_in[0];
    const float* noise =(const float*)d_in[1];
    const float* smu   =(const float*)d_in[2];
    const float* sls   =(const float*)d_in[3];
    const float* Wq    =(const float*)d_in[4];
    const float* Wk    =(const float*)d_in[5];
    const float* Wv    =(const float*)d_in[6];
    const float* W_ih  =(const float*)d_in[7];
    const float* W_hh  =(const float*)d_in[8];
    const float* b_ih  =(const float*)d_in[9];
    const float* b_hh  =(const float*)d_in[10];
    const float* W1    =(const float*)d_in[11];
    const float* b1    =(const float*)d_in[12];
    const float* W2    =(const float*)d_in[13];
    const float* b2    =(const float*)d_in[14];
    float* out=(float*)d_out;

    cudaFuncSetAttribute(k_attn, cudaFuncAttributeMaxDynamicSharedMemorySize, ATTN_SMEM_BYTES);

    k_init_proj<<<128,512>>>(noise,smu,sls,Wq,Wk);
    for(int it=0; it<3; it++){
        dim3 g(32,128);
        k_attn<<<g,256,ATTN_SMEM_BYTES>>>(inputs);
        k_update<<<128,512>>>(Wv,W_ih,W_hh,b_ih,b_hh,W1,b1,W2,b2,Wq,Wk,out, it==2);
    }
}